// round 8
// baseline (speedup 1.0000x reference)
#include <cuda_runtime.h>
#include <math.h>

// x[1, 2M, 16] fp32, ~5% NaN. Per-column mean of valid entries; NaNs -> mean.
//
// Single persistent kernel:
//   phase1: stream own tile ONCE: accumulate per-column sum/count, raw
//           copy x -> out (__stcs), and append block-local offsets of
//           NaN-containing float4s to a compacted shared-memory list.
//   grid barrier
//   phase2: warp-dense walk of the list: reload flagged float4, replace
//           NaN components with column mean, store. (~18.5% of float4s)

#define C 16
#define THREADS 256
#define MAX_CHUNK 16384   // max float4s per block (ushort offsets, 32KB list)

struct Acc {
    float sum[C];
    float cnt[C];
    unsigned int counter;
};
__device__ Acc g_acc;

__global__ void __launch_bounds__(THREADS)
fused_kernel(const float4* __restrict__ in, float4* __restrict__ out,
             long long n4, long long chunk) {
    __shared__ float s_sum[C];
    __shared__ float s_cnt[C];
    __shared__ float s_mean[C];
    __shared__ int   s_nflag;
    __shared__ unsigned short s_list[MAX_CHUNK];

    const int t = threadIdx.x;
    if (t < C) { s_sum[t] = 0.0f; s_cnt[t] = 0.0f; }
    if (t == 0) s_nflag = 0;
    __syncthreads();

    const long long base  = (long long)blockIdx.x * chunk;
    const long long end   = (base + chunk < n4) ? (base + chunk) : n4;
    const long long start = base + t;

    const int cg    = (int)(start & 3);   // loop-invariant column group
    const int cbase = cg * 4;

    float ls0 = 0.f, ls1 = 0.f, ls2 = 0.f, ls3 = 0.f;
    float lc0 = 0.f, lc1 = 0.f, lc2 = 0.f, lc3 = 0.f;

    // ---------- phase 1: single streaming pass + flag list ----------
    #pragma unroll 4
    for (long long i = start; i < end; i += THREADS) {
        float4 v = in[i];
        bool v0 = (v.x == v.x);
        bool v1 = (v.y == v.y);
        bool v2 = (v.z == v.z);
        bool v3 = (v.w == v.w);
        if (v0) { ls0 += v.x; lc0 += 1.f; }
        if (v1) { ls1 += v.y; lc1 += 1.f; }
        if (v2) { ls2 += v.z; lc2 += 1.f; }
        if (v3) { ls3 += v.w; lc3 += 1.f; }
        __stcs(&out[i], v);               // raw copy-through
        if (!(v0 && v1 && v2 && v3)) {
            int slot = atomicAdd(&s_nflag, 1);
            s_list[slot] = (unsigned short)(i - base);
        }
    }

    atomicAdd(&s_sum[cbase + 0], ls0);
    atomicAdd(&s_sum[cbase + 1], ls1);
    atomicAdd(&s_sum[cbase + 2], ls2);
    atomicAdd(&s_sum[cbase + 3], ls3);
    atomicAdd(&s_cnt[cbase + 0], lc0);
    atomicAdd(&s_cnt[cbase + 1], lc1);
    atomicAdd(&s_cnt[cbase + 2], lc2);
    atomicAdd(&s_cnt[cbase + 3], lc3);
    __syncthreads();

    if (t < C) {
        atomicAdd(&g_acc.sum[t], s_sum[t]);
        atomicAdd(&g_acc.cnt[t], s_cnt[t]);
        __threadfence();
    }
    __syncthreads();

    // ---------- grid barrier ----------
    if (t == 0) {
        atomicAdd(&g_acc.counter, 1u);
        volatile unsigned int* ctr = &g_acc.counter;
        while (*ctr < gridDim.x) {
            __nanosleep(64);
        }
        __threadfence();
    }
    __syncthreads();

    if (t < C) {
        s_mean[t] = g_acc.sum[t] / fmaxf(g_acc.cnt[t], 1.0f);
    }
    __syncthreads();

    // ---------- phase 2: warp-dense fix of flagged float4s ----------
    const int nf = s_nflag;
    for (int j = t; j < nf; j += THREADS) {
        long long i = base + (long long)s_list[j];
        float4 v = in[i];
        int cb = ((int)(i & 3)) * 4;
        if (!(v.x == v.x)) v.x = s_mean[cb + 0];
        if (!(v.y == v.y)) v.y = s_mean[cb + 1];
        if (!(v.z == v.z)) v.z = s_mean[cb + 2];
        if (!(v.w == v.w)) v.w = s_mean[cb + 3];
        out[i] = v;
    }
}

extern "C" void kernel_launch(void* const* d_in, const int* in_sizes, int n_in,
                              void* d_out, int out_size) {
    const float4* in = (const float4*)d_in[0];
    float4* out      = (float4*)d_out;
    long long n  = (long long)in_sizes[0];
    long long n4 = n / 4;

    static int grid = 0;
    static void* acc_ptr = nullptr;
    if (grid == 0) {
        int sm_count = 0;
        cudaDeviceGetAttribute(&sm_count, cudaDevAttrMultiProcessorCount, 0);
        int blocks_per_sm = 0;
        cudaOccupancyMaxActiveBlocksPerMultiprocessor(
            &blocks_per_sm, fused_kernel, THREADS, 0);
        if (blocks_per_sm < 1) blocks_per_sm = 1;
        grid = sm_count * blocks_per_sm;
        // ushort offsets + list capacity: chunk must be <= MAX_CHUNK
        long long min_grid = (n4 + MAX_CHUNK - 1) / MAX_CHUNK;
        if (grid < (int)min_grid) grid = (int)min_grid;
        cudaGetSymbolAddress(&acc_ptr, g_acc);
    }

    long long chunk = (n4 + grid - 1) / grid;

    cudaMemsetAsync(acc_ptr, 0, sizeof(Acc));
    fused_kernel<<<grid, THREADS>>>(in, out, n4, chunk);
}

// round 9
// speedup vs baseline: 1.1225x; 1.1225x over previous
#include <cuda_runtime.h>
#include <math.h>

// x[1, 2M, 16] fp32, ~5% NaN. Per-column mean of valid entries; NaNs -> mean.
//
// Uniform two-phase streaming, single persistent kernel:
//   phase1: work-stealing tiles -> per-column sum/count (register acc,
//           one shared+global merge per block)
//   grid barrier (spin)
//   phase2: work-stealing tiles -> reload, NaN->mean, store (.cs hints)
// Last finishing block resets all global state (no memset node needed).

#define C 16
#define THREADS 256
#define TILE 2048LL   // float4s per work tile (32 KB)

struct Acc {
    float sum[C];
    float cnt[C];
    unsigned int barrier_ctr;
    unsigned int w1;       // phase-1 ticket
    unsigned int w2;       // phase-2 ticket
    unsigned int done;     // completion ticket
};
__device__ Acc g_acc;      // static-zeroed; self-reset after each run

__global__ void __launch_bounds__(THREADS)
fused_kernel(const float4* __restrict__ in, float4* __restrict__ out,
             long long n4) {
    __shared__ float s_sum[C];
    __shared__ float s_cnt[C];
    __shared__ float s_mean[C];
    __shared__ unsigned int s_tile;

    const int t = threadIdx.x;
    if (t < C) { s_sum[t] = 0.0f; s_cnt[t] = 0.0f; }
    __syncthreads();

    const unsigned int n_tiles = (unsigned int)((n4 + TILE - 1) / TILE);
    const int cbase = (t & 3) * 4;   // TILE multiple of 4 -> column group fixed

    float ls0 = 0.f, ls1 = 0.f, ls2 = 0.f, ls3 = 0.f;
    float lc0 = 0.f, lc1 = 0.f, lc2 = 0.f, lc3 = 0.f;

    // ---------- phase 1: work-stealing reduction ----------
    for (;;) {
        if (t == 0) s_tile = atomicAdd(&g_acc.w1, 1u);
        __syncthreads();
        unsigned int tile = s_tile;
        __syncthreads();
        if (tile >= n_tiles) break;

        long long base = (long long)tile * TILE;
        long long end  = base + TILE < n4 ? base + TILE : n4;
        #pragma unroll 4
        for (long long i = base + t; i < end; i += THREADS) {
            float4 v = in[i];
            if (v.x == v.x) { ls0 += v.x; lc0 += 1.f; }
            if (v.y == v.y) { ls1 += v.y; lc1 += 1.f; }
            if (v.z == v.z) { ls2 += v.z; lc2 += 1.f; }
            if (v.w == v.w) { ls3 += v.w; lc3 += 1.f; }
        }
    }

    atomicAdd(&s_sum[cbase + 0], ls0);
    atomicAdd(&s_sum[cbase + 1], ls1);
    atomicAdd(&s_sum[cbase + 2], ls2);
    atomicAdd(&s_sum[cbase + 3], ls3);
    atomicAdd(&s_cnt[cbase + 0], lc0);
    atomicAdd(&s_cnt[cbase + 1], lc1);
    atomicAdd(&s_cnt[cbase + 2], lc2);
    atomicAdd(&s_cnt[cbase + 3], lc3);
    __syncthreads();

    if (t < C) {
        atomicAdd(&g_acc.sum[t], s_sum[t]);
        atomicAdd(&g_acc.cnt[t], s_cnt[t]);
        __threadfence();
    }
    __syncthreads();

    // ---------- grid barrier ----------
    if (t == 0) {
        atomicAdd(&g_acc.barrier_ctr, 1u);
        volatile unsigned int* ctr = &g_acc.barrier_ctr;
        while (*ctr < gridDim.x) {
            __nanosleep(64);
        }
        __threadfence();
    }
    __syncthreads();

    if (t < C) {
        s_mean[t] = g_acc.sum[t] / fmaxf(g_acc.cnt[t], 1.0f);
    }
    __syncthreads();

    const float m0 = s_mean[cbase + 0];
    const float m1 = s_mean[cbase + 1];
    const float m2 = s_mean[cbase + 2];
    const float m3 = s_mean[cbase + 3];

    // ---------- phase 2: work-stealing fill ----------
    for (;;) {
        if (t == 0) s_tile = atomicAdd(&g_acc.w2, 1u);
        __syncthreads();
        unsigned int tile = s_tile;
        __syncthreads();
        if (tile >= n_tiles) break;

        long long base = (long long)tile * TILE;
        long long end  = base + TILE < n4 ? base + TILE : n4;
        #pragma unroll 4
        for (long long i = base + t; i < end; i += THREADS) {
            float4 v = __ldcs(&in[i]);
            if (!(v.x == v.x)) v.x = m0;
            if (!(v.y == v.y)) v.y = m1;
            if (!(v.z == v.z)) v.z = m2;
            if (!(v.w == v.w)) v.w = m3;
            __stcs(&out[i], v);
        }
    }

    // ---------- self-reset by last block ----------
    __syncthreads();
    if (t == 0) {
        __threadfence();
        unsigned int ticket = atomicAdd(&g_acc.done, 1u);
        if (ticket == gridDim.x - 1) {
            #pragma unroll
            for (int c = 0; c < C; c++) { g_acc.sum[c] = 0.0f; g_acc.cnt[c] = 0.0f; }
            g_acc.barrier_ctr = 0u;
            g_acc.w1 = 0u;
            g_acc.w2 = 0u;
            g_acc.done = 0u;
            __threadfence();
        }
    }
}

extern "C" void kernel_launch(void* const* d_in, const int* in_sizes, int n_in,
                              void* d_out, int out_size) {
    const float4* in = (const float4*)d_in[0];
    float4* out      = (float4*)d_out;
    long long n  = (long long)in_sizes[0];
    long long n4 = n / 4;

    static int grid = 0;
    if (grid == 0) {
        int sm_count = 0;
        cudaDeviceGetAttribute(&sm_count, cudaDevAttrMultiProcessorCount, 0);
        int blocks_per_sm = 0;
        cudaOccupancyMaxActiveBlocksPerMultiprocessor(
            &blocks_per_sm, fused_kernel, THREADS, 0);
        if (blocks_per_sm < 1) blocks_per_sm = 1;
        grid = sm_count * blocks_per_sm;
    }

    fused_kernel<<<grid, THREADS>>>(in, out, n4);
}